// round 1
// baseline (speedup 1.0000x reference)
#include <cuda_runtime.h>
#include <cfloat>
#include <math.h>

// Problem constants
constexpr int H = 96, W = 96, B = 8;
constexpr int CIN1 = 320;    // N + M = 128 + 192
constexpr int NCH  = 128;    // N
constexpr int MKCH = 576;    // M*K

// Scratch (static device allocations — allowed)
__device__ float g_cat [B * CIN1 * H * W];   // concat(up(z2), y1)
__device__ float g_buf1[B * NCH  * H * W];
__device__ float g_buf2[B * NCH  * H * W];
__device__ float g_max [B * MKCH];

// ---------------------------------------------------------------------------
// Upsample bilinear x4 (align-corners style, matching jnp.linspace) + concat
// ---------------------------------------------------------------------------
__global__ void upsample_concat_kernel(const float* __restrict__ z2,
                                       const float* __restrict__ y1,
                                       float* __restrict__ cat)
{
    int idx = blockIdx.x * blockDim.x + threadIdx.x;
    int total = B * CIN1 * H * W;
    if (idx >= total) return;
    int x = idx % W;
    int y = (idx / W) % H;
    int c = (idx / (W * H)) % CIN1;
    int b = idx / (W * H * CIN1);

    float v;
    if (c < NCH) {
        const float step = 23.0f / 95.0f;   // (h-1)/(H-1)
        float ys = (float)y * step;
        float xs = (float)x * step;
        int y0 = (int)floorf(ys);
        int x0 = (int)floorf(xs);
        if (y0 > 23) y0 = 23;
        if (x0 > 23) x0 = 23;
        int y1i = min(y0 + 1, 23);
        int x1i = min(x0 + 1, 23);
        float wy = ys - (float)y0;
        float wx = xs - (float)x0;
        const float* zc = z2 + ((size_t)(b * NCH + c) * 24) * 24;
        float a00 = zc[y0 * 24 + x0];
        float a01 = zc[y0 * 24 + x1i];
        float a10 = zc[y1i * 24 + x0];
        float a11 = zc[y1i * 24 + x1i];
        float top = a00 * (1.0f - wx) + a01 * wx;
        float bot = a10 * (1.0f - wx) + a11 * wx;
        v = top * (1.0f - wy) + bot * wy;
    } else {
        v = y1[((size_t)(b * 192 + (c - NCH)) * H + y) * W + x];
    }
    cat[idx] = v;
}

__global__ void init_max_kernel(float* __restrict__ mx)
{
    int i = blockIdx.x * blockDim.x + threadIdx.x;
    if (i < B * MKCH) mx[i] = -FLT_MAX;
}

__device__ __forceinline__ void atomicMaxFloat(float* addr, float val)
{
    int old = __float_as_int(*addr);
    while (__int_as_float(old) < val) {
        int assumed = old;
        old = atomicCAS((int*)addr, assumed, __float_as_int(val));
        if (old == assumed) break;
    }
}

// ---------------------------------------------------------------------------
// Direct 5x5 conv, pad=2, stride 1, H=W=96, B=8.
// Block: 32x32 spatial tile x 16 out-channels, one batch.
// 256 threads: tid&3 -> oc quad (4 ocs each), tid>>2 -> 8x8 spatial (4x4 patch).
// ACT: 0=none, 1=relu, 2=lrelu(0.01). MAXRED: reduce spatial max instead of store.
// ---------------------------------------------------------------------------
template <int CIN, int ACT, bool MAXRED>
__global__ __launch_bounds__(256, 2)
void conv5x5_kernel(const float* __restrict__ in,
                    const float* __restrict__ wgt,
                    const float* __restrict__ bias,
                    float* __restrict__ out,
                    float* __restrict__ maxout,
                    int COUT)
{
    __shared__ float s_in[36 * 36];
    __shared__ float s_w[16 * 25];
    __shared__ float s_red[MAXRED ? (16 * 64) : 1];

    const int tid   = threadIdx.x;
    const int tileX = (blockIdx.x % 3) * 32;
    const int tileY = (blockIdx.x / 3) * 32;
    const int ocg   = blockIdx.y;
    const int b     = blockIdx.z;
    const int oc_sub = tid & 3;
    const int sp     = tid >> 2;
    const int spx    = (sp & 7) * 4;
    const int spy    = (sp >> 3) * 4;

    float acc[4][16];
#pragma unroll
    for (int o = 0; o < 4; ++o)
#pragma unroll
        for (int i = 0; i < 16; ++i) acc[o][i] = 0.0f;

    const float* inb = in + (size_t)b * CIN * H * W;
    const float* wb  = wgt + (size_t)(ocg * 16) * CIN * 25;

    for (int cin = 0; cin < CIN; ++cin) {
        // stage input tile (with halo) and the 16x25 weight slice
        const float* inc = inb + (size_t)cin * H * W;
        for (int i = tid; i < 36 * 36; i += 256) {
            int r = i / 36, c = i % 36;
            int gy = tileY - 2 + r;
            int gx = tileX - 2 + c;
            float v = 0.0f;
            if ((unsigned)gy < (unsigned)H && (unsigned)gx < (unsigned)W)
                v = inc[gy * W + gx];
            s_in[i] = v;
        }
        for (int i = tid; i < 400; i += 256) {
            int r = i / 25, t = i % 25;
            s_w[i] = wb[(size_t)r * CIN * 25 + cin * 25 + t];
        }
        __syncthreads();

#pragma unroll
        for (int kh = 0; kh < 5; ++kh) {
            float iv[4][8];
#pragma unroll
            for (int py = 0; py < 4; ++py)
#pragma unroll
                for (int c = 0; c < 8; ++c)
                    iv[py][c] = s_in[(spy + py + kh) * 36 + spx + c];
#pragma unroll
            for (int kw = 0; kw < 5; ++kw) {
                float wv[4];
#pragma unroll
                for (int o = 0; o < 4; ++o)
                    wv[o] = s_w[(oc_sub * 4 + o) * 25 + kh * 5 + kw];
#pragma unroll
                for (int py = 0; py < 4; ++py)
#pragma unroll
                    for (int px = 0; px < 4; ++px) {
                        float xv = iv[py][px + kw];
#pragma unroll
                        for (int o = 0; o < 4; ++o)
                            acc[o][py * 4 + px] = fmaf(wv[o], xv, acc[o][py * 4 + px]);
                    }
            }
        }
        __syncthreads();
    }

    // epilogue
    const int oc0 = ocg * 16 + oc_sub * 4;

    if (!MAXRED) {
#pragma unroll
        for (int o = 0; o < 4; ++o) {
            float bv = bias[oc0 + o];
#pragma unroll
            for (int py = 0; py < 4; ++py) {
                float4 v4;
                float* vp = &v4.x;
#pragma unroll
                for (int px = 0; px < 4; ++px) {
                    float v = acc[o][py * 4 + px] + bv;
                    if (ACT == 1) v = fmaxf(v, 0.0f);
                    else if (ACT == 2) v = (v >= 0.0f) ? v : 0.01f * v;
                    vp[px] = v;
                }
                float* op = out + (((size_t)b * COUT + oc0 + o) * H + (tileY + spy + py)) * W
                                + (tileX + spx);
                *reinterpret_cast<float4*>(op) = v4;
            }
        }
    } else {
#pragma unroll
        for (int o = 0; o < 4; ++o) {
            float bv = bias[oc0 + o];
            float m = -FLT_MAX;
#pragma unroll
            for (int i = 0; i < 16; ++i) m = fmaxf(m, acc[o][i] + bv);
            s_red[(oc_sub * 4 + o) * 64 + sp] = m;
        }
        __syncthreads();
        if (tid < 16) {
            float m = -FLT_MAX;
#pragma unroll 8
            for (int j = 0; j < 64; ++j) m = fmaxf(m, s_red[tid * 64 + j]);
            atomicMaxFloat(&maxout[(size_t)b * COUT + ocg * 16 + tid], m);
        }
    }
}

// ---------------------------------------------------------------------------
// Tail: lrelu(maxvals) -> 1x1 conv 576->576 -> grouped softmax over K=3
// Single block of 576 threads.
// ---------------------------------------------------------------------------
__global__ void finalize_kernel(const float* __restrict__ mx,
                                const float* __restrict__ ww3,
                                const float* __restrict__ bw3,
                                float* __restrict__ outw)
{
    __shared__ float s_g[B * MKCH];
    __shared__ float s_h[B * MKCH];
    int tid = threadIdx.x;   // 576

    for (int i = tid; i < B * MKCH; i += MKCH) {
        float v = mx[i];
        s_g[i] = (v >= 0.0f) ? v : 0.01f * v;
    }
    __syncthreads();

    int oc = tid;
    float bb = bw3[oc];
    float accv[B];
#pragma unroll
    for (int b = 0; b < B; ++b) accv[b] = bb;
    for (int ci = 0; ci < MKCH; ++ci) {
        float w = ww3[(size_t)oc * MKCH + ci];
#pragma unroll
        for (int b = 0; b < B; ++b)
            accv[b] = fmaf(w, s_g[b * MKCH + ci], accv[b]);
    }
#pragma unroll
    for (int b = 0; b < B; ++b) s_h[b * MKCH + oc] = accv[b];
    __syncthreads();

    if (tid < 192) {
        int m = tid;
        for (int b = 0; b < B; ++b) {
            float a0 = s_h[b * MKCH + m];
            float a1 = s_h[b * MKCH + 192 + m];
            float a2 = s_h[b * MKCH + 384 + m];
            float mxv = fmaxf(a0, fmaxf(a1, a2));
            float e0 = expf(a0 - mxv);
            float e1 = expf(a1 - mxv);
            float e2 = expf(a2 - mxv);
            float s = e0 + e1 + e2;
            outw[(size_t)b * MKCH + m]        = e0 / s;
            outw[(size_t)b * MKCH + 192 + m]  = e1 / s;
            outw[(size_t)b * MKCH + 384 + m]  = e2 / s;
        }
    }
}

// ---------------------------------------------------------------------------
extern "C" void kernel_launch(void* const* d_in, const int* in_sizes, int n_in,
                              void* d_out, int out_size)
{
    const float* z2  = (const float*)d_in[0];
    const float* y1  = (const float*)d_in[1];
    const float* ws1 = (const float*)d_in[2];  const float* bs1 = (const float*)d_in[3];
    const float* ws2 = (const float*)d_in[4];  const float* bs2 = (const float*)d_in[5];
    const float* ws3 = (const float*)d_in[6];  const float* bs3 = (const float*)d_in[7];
    const float* wm1 = (const float*)d_in[8];  const float* bm1 = (const float*)d_in[9];
    const float* wm2 = (const float*)d_in[10]; const float* bm2 = (const float*)d_in[11];
    const float* wm3 = (const float*)d_in[12]; const float* bm3 = (const float*)d_in[13];
    const float* ww1 = (const float*)d_in[14]; const float* bw1 = (const float*)d_in[15];
    const float* ww2 = (const float*)d_in[16]; const float* bw2 = (const float*)d_in[17];
    const float* ww3 = (const float*)d_in[18]; const float* bw3 = (const float*)d_in[19];

    float* out   = (float*)d_out;
    float* sigma = out;
    float* means = out + (size_t)B * MKCH * H * W;
    float* wout  = out + 2 * (size_t)B * MKCH * H * W;

    float *cat, *b1, *b2, *mx;
    cudaGetSymbolAddress((void**)&cat, g_cat);
    cudaGetSymbolAddress((void**)&b1,  g_buf1);
    cudaGetSymbolAddress((void**)&b2,  g_buf2);
    cudaGetSymbolAddress((void**)&mx,  g_max);

    int total_cat = B * CIN1 * H * W;
    upsample_concat_kernel<<<(total_cat + 255) / 256, 256>>>(z2, y1, cat);
    init_max_kernel<<<(B * MKCH + 255) / 256, 256>>>(mx);

    dim3 blk(256);
    dim3 g128(9, 8, 8);
    dim3 g576(9, 36, 8);

    // sigma branch: relu chain
    conv5x5_kernel<CIN1, 1, false><<<g128, blk>>>(cat, ws1, bs1, b1, nullptr, NCH);
    conv5x5_kernel<NCH,  1, false><<<g128, blk>>>(b1,  ws2, bs2, b2, nullptr, NCH);
    conv5x5_kernel<NCH,  1, false><<<g576, blk>>>(b2,  ws3, bs3, sigma, nullptr, MKCH);

    // means branch: lrelu, lrelu, none
    conv5x5_kernel<CIN1, 2, false><<<g128, blk>>>(cat, wm1, bm1, b1, nullptr, NCH);
    conv5x5_kernel<NCH,  2, false><<<g128, blk>>>(b1,  wm2, bm2, b2, nullptr, NCH);
    conv5x5_kernel<NCH,  0, false><<<g576, blk>>>(b2,  wm3, bm3, means, nullptr, MKCH);

    // weights branch: lrelu, conv + global max, then 1x1 + softmax
    conv5x5_kernel<CIN1, 2, false><<<g128, blk>>>(cat, ww1, bw1, b1, nullptr, NCH);
    conv5x5_kernel<NCH,  0, true ><<<g576, blk>>>(b1,  ww2, bw2, nullptr, mx, MKCH);
    finalize_kernel<<<1, MKCH>>>(mx, ww3, bw3, wout);
}

// round 4
// speedup vs baseline: 1.6495x; 1.6495x over previous
#include <cuda_runtime.h>
#include <cuda_fp16.h>
#include <mma.h>
#include <cstdint>
#include <cfloat>
#include <math.h>

using namespace nvcuda;

// ---------------------------------------------------------------------------
// Problem constants
// ---------------------------------------------------------------------------
constexpr int Hh = 96, Ww = 96, Bb = 8;
constexpr int CIN1 = 320;    // N + M
constexpr int NCH  = 128;
constexpr int MKCH = 576;
constexpr int HP = 100, WP = 128;         // padded NHWC layout
constexpr int PB = HP * WP;               // 12800 pixels per batch
constexpr int PTOT = Bb * PB;             // 102400
constexpr int GUARD = WP;                 // guard pixels each side

// Scratch (static device allocations)
__device__ __half g_cat [(PTOT + 2 * GUARD) * CIN1];
__device__ __half g_act1[(PTOT + 2 * GUARD) * NCH];
__device__ __half g_act2[(PTOT + 2 * GUARD) * NCH];
__device__ __half g_wt  [9420800];
__device__ float  g_max [Bb * MKCH];

// weight scratch offsets (elements)
constexpr size_t WT_S1 = 0;
constexpr size_t WT_S2 = WT_S1 + 25ull*128*320;
constexpr size_t WT_S3 = WT_S2 + 25ull*128*128;
constexpr size_t WT_M1 = WT_S3 + 25ull*576*128;
constexpr size_t WT_M2 = WT_M1 + 25ull*128*320;
constexpr size_t WT_M3 = WT_M2 + 25ull*128*128;
constexpr size_t WT_W1 = WT_M3 + 25ull*576*128;
constexpr size_t WT_W2 = WT_W1 + 25ull*128*320;

// ---------------------------------------------------------------------------
// Prep kernels
// ---------------------------------------------------------------------------
__global__ void pack_cat_kernel(const float* __restrict__ z2,
                                const float* __restrict__ y1,
                                __half* __restrict__ cat)   // cat points at pixel 0
{
    int p = blockIdx.x;
    int c = threadIdx.x;                 // 0..319
    int b = p / PB;
    int rem = p % PB;
    int yp = rem / WP, xp = rem % WP;
    float v = 0.0f;
    if (yp >= 2 && yp < 98 && xp >= 2 && xp < 98) {
        int y = yp - 2, x = xp - 2;
        if (c < NCH) {
            const float step = 23.0f / 95.0f;
            float ys = (float)y * step, xs = (float)x * step;
            int y0 = (int)floorf(ys); if (y0 > 23) y0 = 23;
            int x0 = (int)floorf(xs); if (x0 > 23) x0 = 23;
            int y1i = min(y0 + 1, 23), x1i = min(x0 + 1, 23);
            float wy = ys - (float)y0, wx = xs - (float)x0;
            const float* zc = z2 + ((size_t)(b * NCH + c) * 24) * 24;
            float a00 = zc[y0 * 24 + x0],  a01 = zc[y0 * 24 + x1i];
            float a10 = zc[y1i * 24 + x0], a11 = zc[y1i * 24 + x1i];
            float top = a00 * (1.0f - wx) + a01 * wx;
            float bot = a10 * (1.0f - wx) + a11 * wx;
            v = top * (1.0f - wy) + bot * wy;
        } else {
            v = y1[((size_t)(b * 192 + (c - NCH)) * Hh + y) * Ww + x];
        }
    }
    cat[(size_t)p * CIN1 + c] = __float2half_rn(v);
}

// clear cat guard pixels (raw base)
__global__ void clear_cat_guard_kernel(__half* __restrict__ catraw)
{
    int p = blockIdx.x;       // 0..2*GUARD-1
    int pix = (p < GUARD) ? p : (GUARD + PTOT + (p - GUARD));
    catraw[(size_t)pix * CIN1 + threadIdx.x] = __float2half_rn(0.0f);
}

// clear pads + guards of an act buffer (raw base)
__global__ void clear_act_kernel(__half* __restrict__ a)
{
    int p = blockIdx.x;       // 0 .. PTOT+2*GUARD-1
    bool z;
    if (p < GUARD || p >= GUARD + PTOT) z = true;
    else {
        int rem = (p - GUARD) % PB;
        int yp = rem / WP, xp = rem % WP;
        z = (yp < 2 || yp >= 98 || xp < 2 || xp >= 98);
    }
    if (z) a[(size_t)p * NCH + threadIdx.x] = __float2half_rn(0.0f);
}

// transpose weights [Cout][Cin][5][5] -> [25][Cout][Cin], fp16
__global__ void wtrans_kernel(const float* __restrict__ w, __half* __restrict__ o,
                              int Cout, int Cin)
{
    int idx = blockIdx.x * blockDim.x + threadIdx.x;
    int total = Cout * Cin * 25;
    if (idx >= total) return;
    int khw = idx % 25;
    int t = idx / 25;
    int ci = t % Cin;
    int oc = t / Cin;
    o[(size_t)khw * Cout * Cin + (size_t)oc * Cin + ci] = __float2half_rn(w[idx]);
}

__global__ void init_max_kernel(float* __restrict__ mx)
{
    int i = blockIdx.x * blockDim.x + threadIdx.x;
    if (i < Bb * MKCH) mx[i] = -FLT_MAX;
}

__device__ __forceinline__ void atomicMaxFloat(float* addr, float val)
{
    int old = __float_as_int(*addr);
    while (__int_as_float(old) < val) {
        int assumed = old;
        old = atomicCAS((int*)addr, assumed, __float_as_int(val));
        if (old == assumed) break;
    }
}

// ---------------------------------------------------------------------------
// wmma fp16 implicit-GEMM conv.
// CTA: M=128 pixels (one padded image row), N=NOC out chans. 256 thr, 8 warps 4x2.
// Warp tile: 32 x (NOC/2). K = 25 taps x CIN.
// A,B fragments loaded straight from global (L1-resident tiles).
// OMODE: 0 = fp16 NHWC scratch, 1 = fp32 NCHW d_out, 2 = global-max reduce
// ACT:   0 none, 1 relu, 2 lrelu
// ---------------------------------------------------------------------------
template <int CIN, int NOC, int COUT, int ACT, int OMODE>
__global__ void __launch_bounds__(256, 1)
conv_wmma_kernel(const __half* __restrict__ ain,   // pixel 0
                 const __half* __restrict__ wt,
                 const float* __restrict__ bias,
                 float* __restrict__ outf,         // OMODE 1
                 __half* __restrict__ outh,        // OMODE 0
                 float* __restrict__ gmax)         // OMODE 2
{
    extern __shared__ float sres[];                // [128][NOCP]
    constexpr int NOCP = NOC + 8;
    constexpr int WTN = NOC / 32;                  // b-tiles per warp (4 or 6)
    constexpr int WNS = NOC / 2;                   // warp N span

    const int tid  = threadIdx.x;
    const int wid  = tid >> 5;
    const int wm   = wid & 3;
    const int wn   = wid >> 2;

    const int b   = blockIdx.x / 96;
    const int y   = blockIdx.x % 96;
    const int oc0 = blockIdx.y * NOC;
    const int pbase = (b * HP + y + 2) * WP;

    wmma::fragment<wmma::accumulator, 16, 16, 16, float> acc[2][WTN];
#pragma unroll
    for (int t = 0; t < 2; ++t)
#pragma unroll
        for (int j = 0; j < WTN; ++j) wmma::fill_fragment(acc[t][j], 0.0f);

#pragma unroll 1
    for (int khw = 0; khw < 25; ++khw) {
        const int kh = khw / 5, kw = khw % 5;
        const __half* pa = ain + ((long)pbase + (kh - 2) * WP + (kw - 2) + wm * 32) * CIN;
        const __half* pb = wt + ((size_t)khw * COUT + oc0 + wn * WNS) * CIN;

#pragma unroll 4
        for (int kk = 0; kk < CIN / 16; ++kk) {
            wmma::fragment<wmma::matrix_a, 16, 16, 16, __half, wmma::row_major> af[2];
            wmma::fragment<wmma::matrix_b, 16, 16, 16, __half, wmma::col_major> bf[WTN];
            wmma::load_matrix_sync(af[0], pa + kk * 16, CIN);
            wmma::load_matrix_sync(af[1], pa + 16 * CIN + kk * 16, CIN);
#pragma unroll
            for (int j = 0; j < WTN; ++j)
                wmma::load_matrix_sync(bf[j], pb + (size_t)j * 16 * CIN + kk * 16, CIN);
#pragma unroll
            for (int t = 0; t < 2; ++t)
#pragma unroll
                for (int j = 0; j < WTN; ++j)
                    wmma::mma_sync(acc[t][j], af[t], bf[j], acc[t][j]);
        }
    }

    // ---- epilogue through smem ----
#pragma unroll
    for (int t = 0; t < 2; ++t)
#pragma unroll
        for (int j = 0; j < WTN; ++j) {
            int row = wm * 32 + t * 16;
            int col = wn * WNS + j * 16;
            wmma::store_matrix_sync(&sres[row * NOCP + col], acc[t][j], NOCP,
                                    wmma::mem_row_major);
        }
    __syncthreads();

    if (OMODE == 0) {
        // oc fastest -> coalesced fp16 NHWC writes (NOC == 128 here)
        for (int i = tid; i < 128 * NOC; i += 256) {
            int oc  = i & (NOC - 1);
            int pix = i >> 7;
            if (pix >= 2 && pix < 98) {
                float v = sres[pix * NOCP + oc] + bias[oc0 + oc];
                if (ACT == 1) v = fmaxf(v, 0.0f);
                else if (ACT == 2) v = (v >= 0.0f) ? v : 0.01f * v;
                outh[(size_t)(pbase + pix) * NCH + oc0 + oc] = __float2half_rn(v);
            }
        }
    } else if (OMODE == 1) {
        // x fastest within oc -> coalesced fp32 NCHW writes
        for (int i = tid; i < 128 * NOC; i += 256) {
            int oc = i >> 7;
            int xp = i & 127;
            if (xp >= 2 && xp < 98) {
                float v = sres[xp * NOCP + oc] + bias[oc0 + oc];
                if (ACT == 1) v = fmaxf(v, 0.0f);
                else if (ACT == 2) v = (v >= 0.0f) ? v : 0.01f * v;
                outf[(((size_t)b * COUT + oc0 + oc) * Hh + y) * Ww + (xp - 2)] = v;
            }
        }
    } else {
        if (tid < NOC) {
            int oc = tid;
            float bv = bias[oc0 + oc];
            float m = -FLT_MAX;
            for (int pix = 2; pix < 98; ++pix)
                m = fmaxf(m, sres[pix * NOCP + oc] + bv);
            atomicMaxFloat(&gmax[(size_t)b * MKCH + oc0 + oc], m);
        }
    }
}

// ---------------------------------------------------------------------------
// Tail: lrelu(max) -> 1x1 conv 576->576 -> grouped softmax K=3 (fp32, exact)
// ---------------------------------------------------------------------------
__global__ void finalize_kernel(const float* __restrict__ mx,
                                const float* __restrict__ ww3,
                                const float* __restrict__ bw3,
                                float* __restrict__ outw)
{
    __shared__ float s_g[Bb * MKCH];
    __shared__ float s_h[Bb * MKCH];
    int tid = threadIdx.x;   // 576

    for (int i = tid; i < Bb * MKCH; i += MKCH) {
        float v = mx[i];
        s_g[i] = (v >= 0.0f) ? v : 0.01f * v;
    }
    __syncthreads();

    float bb = bw3[tid];
    float accv[Bb];
#pragma unroll
    for (int b = 0; b < Bb; ++b) accv[b] = bb;
    for (int ci = 0; ci < MKCH; ++ci) {
        float w = ww3[(size_t)tid * MKCH + ci];
#pragma unroll
        for (int b = 0; b < Bb; ++b)
            accv[b] = fmaf(w, s_g[b * MKCH + ci], accv[b]);
    }
#pragma unroll
    for (int b = 0; b < Bb; ++b) s_h[b * MKCH + tid] = accv[b];
    __syncthreads();

    if (tid < 192) {
        int m = tid;
        for (int b = 0; b < Bb; ++b) {
            float a0 = s_h[b * MKCH + m];
            float a1 = s_h[b * MKCH + 192 + m];
            float a2 = s_h[b * MKCH + 384 + m];
            float mxv = fmaxf(a0, fmaxf(a1, a2));
            float e0 = expf(a0 - mxv), e1 = expf(a1 - mxv), e2 = expf(a2 - mxv);
            float s = e0 + e1 + e2;
            outw[(size_t)b * MKCH + m]       = e0 / s;
            outw[(size_t)b * MKCH + 192 + m] = e1 / s;
            outw[(size_t)b * MKCH + 384 + m] = e2 / s;
        }
    }
}

// ---------------------------------------------------------------------------
extern "C" void kernel_launch(void* const* d_in, const int* in_sizes, int n_in,
                              void* d_out, int out_size)
{
    const float* z2  = (const float*)d_in[0];
    const float* y1  = (const float*)d_in[1];
    const float* ws1 = (const float*)d_in[2];  const float* bs1 = (const float*)d_in[3];
    const float* ws2 = (const float*)d_in[4];  const float* bs2 = (const float*)d_in[5];
    const float* ws3 = (const float*)d_in[6];  const float* bs3 = (const float*)d_in[7];
    const float* wm1 = (const float*)d_in[8];  const float* bm1 = (const float*)d_in[9];
    const float* wm2 = (const float*)d_in[10]; const float* bm2 = (const float*)d_in[11];
    const float* wm3 = (const float*)d_in[12]; const float* bm3 = (const float*)d_in[13];
    const float* ww1 = (const float*)d_in[14]; const float* bw1 = (const float*)d_in[15];
    const float* ww2 = (const float*)d_in[16]; const float* bw2 = (const float*)d_in[17];
    const float* ww3 = (const float*)d_in[18]; const float* bw3 = (const float*)d_in[19];

    float* out   = (float*)d_out;
    float* sigma = out;
    float* means = out + (size_t)Bb * MKCH * Hh * Ww;
    float* wout  = out + 2 * (size_t)Bb * MKCH * Hh * Ww;

    __half *catraw, *a1raw, *a2raw, *wtb;
    float *mx;
    cudaGetSymbolAddress((void**)&catraw, g_cat);
    cudaGetSymbolAddress((void**)&a1raw,  g_act1);
    cudaGetSymbolAddress((void**)&a2raw,  g_act2);
    cudaGetSymbolAddress((void**)&wtb,    g_wt);
    cudaGetSymbolAddress((void**)&mx,     g_max);

    __half* cat = catraw + (size_t)GUARD * CIN1;
    __half* a1  = a1raw  + (size_t)GUARD * NCH;
    __half* a2  = a2raw  + (size_t)GUARD * NCH;

    constexpr int SM128 = 128 * (128 + 8) * 4;   // 69632
    constexpr int SM192 = 128 * (192 + 8) * 4;   // 102400
    cudaFuncSetAttribute(conv_wmma_kernel<320,128,128,1,0>, cudaFuncAttributeMaxDynamicSharedMemorySize, SM128);
    cudaFuncSetAttribute(conv_wmma_kernel<320,128,128,2,0>, cudaFuncAttributeMaxDynamicSharedMemorySize, SM128);
    cudaFuncSetAttribute(conv_wmma_kernel<128,128,128,1,0>, cudaFuncAttributeMaxDynamicSharedMemorySize, SM128);
    cudaFuncSetAttribute(conv_wmma_kernel<128,128,128,2,0>, cudaFuncAttributeMaxDynamicSharedMemorySize, SM128);
    cudaFuncSetAttribute(conv_wmma_kernel<128,192,576,1,1>, cudaFuncAttributeMaxDynamicSharedMemorySize, SM192);
    cudaFuncSetAttribute(conv_wmma_kernel<128,192,576,0,1>, cudaFuncAttributeMaxDynamicSharedMemorySize, SM192);
    cudaFuncSetAttribute(conv_wmma_kernel<128,192,576,0,2>, cudaFuncAttributeMaxDynamicSharedMemorySize, SM192);

    // ---- prep ----
    pack_cat_kernel<<<PTOT, CIN1>>>(z2, y1, cat);
    clear_cat_guard_kernel<<<2 * GUARD, CIN1>>>(catraw);
    clear_act_kernel<<<PTOT + 2 * GUARD, NCH>>>(a1raw);
    clear_act_kernel<<<PTOT + 2 * GUARD, NCH>>>(a2raw);
    init_max_kernel<<<(Bb * MKCH + 255) / 256, 256>>>(mx);

    auto wt = [&](const float* src, size_t off, int Cout, int Cin) {
        int total = Cout * Cin * 25;
        wtrans_kernel<<<(total + 255) / 256, 256>>>(src, wtb + off, Cout, Cin);
    };
    wt(ws1, WT_S1, 128, 320); wt(ws2, WT_S2, 128, 128); wt(ws3, WT_S3, 576, 128);
    wt(wm1, WT_M1, 128, 320); wt(wm2, WT_M2, 128, 128); wt(wm3, WT_M3, 576, 128);
    wt(ww1, WT_W1, 128, 320); wt(ww2, WT_W2, 576, 128);

    dim3 blk(256);
    dim3 g1(Bb * 96, 1);
    dim3 g3(Bb * 96, 3);

    // sigma branch
    conv_wmma_kernel<320,128,128,1,0><<<g1, blk, SM128>>>(cat, wtb + WT_S1, bs1, nullptr, a1, nullptr);
    conv_wmma_kernel<128,128,128,1,0><<<g1, blk, SM128>>>(a1,  wtb + WT_S2, bs2, nullptr, a2, nullptr);
    conv_wmma_kernel<128,192,576,1,1><<<g3, blk, SM192>>>(a2,  wtb + WT_S3, bs3, sigma, nullptr, nullptr);

    // means branch
    conv_wmma_kernel<320,128,128,2,0><<<g1, blk, SM128>>>(cat, wtb + WT_M1, bm1, nullptr, a1, nullptr);
    conv_wmma_kernel<128,128,128,2,0><<<g1, blk, SM128>>>(a1,  wtb + WT_M2, bm2, nullptr, a2, nullptr);
    conv_wmma_kernel<128,192,576,0,1><<<g3, blk, SM192>>>(a2,  wtb + WT_M3, bm3, means, nullptr, nullptr);

    // weights branch
    conv_wmma_kernel<320,128,128,2,0><<<g1, blk, SM128>>>(cat, wtb + WT_W1, bw1, nullptr, a1, nullptr);
    conv_wmma_kernel<128,192,576,0,2><<<g3, blk, SM192>>>(a1,  wtb + WT_W2, bw2, nullptr, nullptr, mx);

    finalize_kernel<<<1, MKCH>>>(mx, ww3, bw3, wout);
}